// round 9
// baseline (speedup 1.0000x reference)
#include <cuda_runtime.h>
#include <cuda_bf16.h>

#define N_NODES 100000

// Scratch (zero-init at load). Replay invariant: deg=0 and g_cnt=0 at entry
// (k_prep / k_node's last block cleaned them); dinv/dw/y/p rewritten by k_prep;
// S zeroed by k_deg.
__device__ unsigned g_deg [N_NODES];
__device__ float    g_dinv[N_NODES];   // read-only during k_edge (gather stream)
__device__ float2   g_dw  [N_NODES];   // .x=dinv, .y=wacc; atomic-only during k_edge
__device__ float4   g_y   [N_NODES];   // x * dinv
__device__ float4   g_p   [N_NODES];   // seeded with y; += y[src] per edge
__device__ float    g_S   [64];
__device__ unsigned g_cnt;             // k_node completion counter (self-resets)

// K1: in-degree count, 8 edges/thread (2x int4, streaming loads). Zeroes S.
__global__ void k_deg(const int4* __restrict__ dst4, int E4) {
    int t = blockIdx.x * blockDim.x + threadIdx.x;
    if (t < 64) g_S[t] = 0.0f;
    int t0 = 2 * t, t1 = 2 * t + 1;
    if (t0 < E4) {
        int4 d = __ldcs(&dst4[t0]);
        if ((unsigned)d.x < (unsigned)N_NODES) atomicAdd(&g_deg[d.x], 1u);
        if ((unsigned)d.y < (unsigned)N_NODES) atomicAdd(&g_deg[d.y], 1u);
        if ((unsigned)d.z < (unsigned)N_NODES) atomicAdd(&g_deg[d.z], 1u);
        if ((unsigned)d.w < (unsigned)N_NODES) atomicAdd(&g_deg[d.w], 1u);
    }
    if (t1 < E4) {
        int4 d = __ldcs(&dst4[t1]);
        if ((unsigned)d.x < (unsigned)N_NODES) atomicAdd(&g_deg[d.x], 1u);
        if ((unsigned)d.y < (unsigned)N_NODES) atomicAdd(&g_deg[d.y], 1u);
        if ((unsigned)d.z < (unsigned)N_NODES) atomicAdd(&g_deg[d.z], 1u);
        if ((unsigned)d.w < (unsigned)N_NODES) atomicAdd(&g_deg[d.w], 1u);
    }
}

// K2: dinv = rsqrt(deg+1); y = x*dinv; seed p = y, dw = {dinv, dinv}.
// Resets deg for next replay.
__global__ void k_prep(const float4* __restrict__ x) {
    int i = blockIdx.x * blockDim.x + threadIdx.x;
    if (i >= N_NODES) return;
    float di = rsqrtf((float)g_deg[i] + 1.0f);
    g_deg[i]  = 0u;                   // self-clean
    g_dinv[i] = di;
    g_dw[i]   = make_float2(di, di);  // wacc seeded with self-loop dinv
    float4 xv = x[i];
    float4 yv = make_float4(xv.x * di, xv.y * di, xv.z * di, xv.w * di);
    g_y[i] = yv;
    g_p[i] = yv;                      // p seeded with self-loop message
}

// K3: fused edge pass, 8 edges/thread (2x int4 per side, streaming loads).
// Per edge: gather y[s] + dinv[d] (batched, MLP=16), then RED.v4 p[d] and
// RED dw[s].y. Gather arrays never share lines with atomic targets.
#define EDGE_ONE(sv, dv, yv, ndv)                                              \
    if ((unsigned)(sv) < (unsigned)N_NODES && (unsigned)(dv) < (unsigned)N_NODES) { \
        asm volatile("red.global.add.v4.f32 [%0], {%1, %2, %3, %4};"           \
                     :: "l"((float*)&g_p[dv]),                                 \
                        "f"((yv).x), "f"((yv).y), "f"((yv).z), "f"((yv).w)     \
                     : "memory");                                              \
        atomicAdd(&g_dw[sv].y, (ndv));                                         \
    }

__global__ void k_edge(const int4* __restrict__ src4,
                       const int4* __restrict__ dst4,
                       int E4) {
    int t = blockIdx.x * blockDim.x + threadIdx.x;
    int t0 = 2 * t, t1 = 2 * t + 1;
    bool h0 = (t0 < E4), h1 = (t1 < E4);
    int4 sA = {0,0,0,0}, dA = {0,0,0,0}, sB = {0,0,0,0}, dB = {0,0,0,0};
    if (h0) { sA = __ldcs(&src4[t0]); dA = __ldcs(&dst4[t0]); }
    if (h1) { sB = __ldcs(&src4[t1]); dB = __ldcs(&dst4[t1]); }
    // batch all gathers (up to 16 loads in flight)
    float4 y0, y1, y2, y3, y4, y5, y6, y7;
    float  n0 = 0.f, n1 = 0.f, n2 = 0.f, n3 = 0.f,
           n4 = 0.f, n5 = 0.f, n6 = 0.f, n7 = 0.f;
    if (h0) {
        if ((unsigned)sA.x < (unsigned)N_NODES) y0 = __ldg(&g_y[sA.x]);
        if ((unsigned)sA.y < (unsigned)N_NODES) y1 = __ldg(&g_y[sA.y]);
        if ((unsigned)sA.z < (unsigned)N_NODES) y2 = __ldg(&g_y[sA.z]);
        if ((unsigned)sA.w < (unsigned)N_NODES) y3 = __ldg(&g_y[sA.w]);
        if ((unsigned)dA.x < (unsigned)N_NODES) n0 = __ldg(&g_dinv[dA.x]);
        if ((unsigned)dA.y < (unsigned)N_NODES) n1 = __ldg(&g_dinv[dA.y]);
        if ((unsigned)dA.z < (unsigned)N_NODES) n2 = __ldg(&g_dinv[dA.z]);
        if ((unsigned)dA.w < (unsigned)N_NODES) n3 = __ldg(&g_dinv[dA.w]);
    }
    if (h1) {
        if ((unsigned)sB.x < (unsigned)N_NODES) y4 = __ldg(&g_y[sB.x]);
        if ((unsigned)sB.y < (unsigned)N_NODES) y5 = __ldg(&g_y[sB.y]);
        if ((unsigned)sB.z < (unsigned)N_NODES) y6 = __ldg(&g_y[sB.z]);
        if ((unsigned)sB.w < (unsigned)N_NODES) y7 = __ldg(&g_y[sB.w]);
        if ((unsigned)dB.x < (unsigned)N_NODES) n4 = __ldg(&g_dinv[dB.x]);
        if ((unsigned)dB.y < (unsigned)N_NODES) n5 = __ldg(&g_dinv[dB.y]);
        if ((unsigned)dB.z < (unsigned)N_NODES) n6 = __ldg(&g_dinv[dB.z]);
        if ((unsigned)dB.w < (unsigned)N_NODES) n7 = __ldg(&g_dinv[dB.w]);
    }
    if (h0) {
        EDGE_ONE(sA.x, dA.x, y0, n0);
        EDGE_ONE(sA.y, dA.y, y1, n1);
        EDGE_ONE(sA.z, dA.z, y2, n2);
        EDGE_ONE(sA.w, dA.w, y3, n3);
    }
    if (h1) {
        EDGE_ONE(sB.x, dB.x, y4, n4);
        EDGE_ONE(sB.y, dB.y, y5, n5);
        EDGE_ONE(sB.z, dB.z, y6, n6);
        EDGE_ONE(sB.w, dB.w, y7, n7);
    }
}

// K4: node pass (transposed, butterfly reduce) + fused final epilogue.
#define KN_BLOCKS 200
#define KN_THREADS 256
#define KN_SPAN (KN_BLOCKS * KN_THREADS)   // 51200
__global__ void __launch_bounds__(KN_THREADS, 2)
k_node(const float* __restrict__ W1, const float* __restrict__ b1,
       const float* __restrict__ W2, const float* __restrict__ b2,
       float* __restrict__ out) {
    __shared__ float4 sW[64];
    __shared__ float  sB[64];
    __shared__ float  sS[64];
    int tid = threadIdx.x;
    if (tid < 64) {
        sW[tid] = make_float4(W1[tid], W1[64 + tid], W1[128 + tid], W1[192 + tid]);
        sB[tid] = b1[tid];
        sS[tid] = 0.0f;
    }
    __syncthreads();

    int t  = blockIdx.x * KN_THREADS + tid;      // [0, 51200)
    int i1 = t + KN_SPAN;
    bool has1 = (i1 < N_NODES);

    float4 p0 = g_p[t];
    float2 d0 = g_dw[t];
    float4 p1 = make_float4(0.f, 0.f, 0.f, 0.f);
    float2 d1 = make_float2(0.f, 0.f);
    if (has1) { p1 = g_p[i1]; d1 = g_dw[i1]; }

    float q0x = d0.x * p0.x, q0y = d0.x * p0.y, q0z = d0.x * p0.z, q0w = d0.x * p0.w;
    float q1x = d1.x * p1.x, q1y = d1.x * p1.y, q1z = d1.x * p1.z, q1w = d1.x * p1.w;
    float wn0 = d0.x * d0.y;
    float wn1 = d1.x * d1.y;

    float acc[64];
    #pragma unroll
    for (int j = 0; j < 64; j++) {
        float4 w = sW[j];
        float  b = sB[j];
        float z0 = fmaf(q0x, w.x, fmaf(q0y, w.y, fmaf(q0z, w.z, fmaf(q0w, w.w, b))));
        float z1 = fmaf(q1x, w.x, fmaf(q1y, w.y, fmaf(q1z, w.z, fmaf(q1w, w.w, b))));
        acc[j] = fmaf(wn0, fmaxf(z0, 0.f), wn1 * fmaxf(z1, 0.f));
    }

    int lane = tid & 31;
    #pragma unroll
    for (int k = 0; k < 32; k++) {
        float lo = acc[k], hi = acc[k + 32];
        bool up = (lane & 16);
        float keep = up ? hi : lo, give = up ? lo : hi;
        acc[k] = keep + __shfl_xor_sync(0xffffffffu, give, 16);
    }
    #pragma unroll
    for (int k = 0; k < 16; k++) {
        float lo = acc[k], hi = acc[k + 16];
        bool up = (lane & 8);
        float keep = up ? hi : lo, give = up ? lo : hi;
        acc[k] = keep + __shfl_xor_sync(0xffffffffu, give, 8);
    }
    #pragma unroll
    for (int k = 0; k < 8; k++) {
        float lo = acc[k], hi = acc[k + 8];
        bool up = (lane & 4);
        float keep = up ? hi : lo, give = up ? lo : hi;
        acc[k] = keep + __shfl_xor_sync(0xffffffffu, give, 4);
    }
    #pragma unroll
    for (int k = 0; k < 4; k++) {
        float lo = acc[k], hi = acc[k + 4];
        bool up = (lane & 2);
        float keep = up ? hi : lo, give = up ? lo : hi;
        acc[k] = keep + __shfl_xor_sync(0xffffffffu, give, 2);
    }
    #pragma unroll
    for (int k = 0; k < 2; k++) {
        float lo = acc[k], hi = acc[k + 2];
        bool up = (lane & 1);
        float keep = up ? hi : lo, give = up ? lo : hi;
        acc[k] = keep + __shfl_xor_sync(0xffffffffu, give, 1);
    }
    int j0 = 32 * ((lane >> 4) & 1) + 16 * ((lane >> 3) & 1)
           +  8 * ((lane >> 2) & 1) +  4 * ((lane >> 1) & 1)
           +  2 * (lane & 1);
    atomicAdd(&sS[j0],     acc[0]);
    atomicAdd(&sS[j0 + 1], acc[1]);
    __syncthreads();
    if (tid < 64) atomicAdd(&g_S[tid], sS[tid]);

    // fused final: last finishing block computes out = (S@W2)/n + b2
    __shared__ bool isLast;
    if (tid == 0) {
        __threadfence();
        isLast = (atomicAdd(&g_cnt, 1u) == KN_BLOCKS - 1);
    }
    __syncthreads();
    if (isLast) {
        __shared__ float fS[64];
        if (tid < 64) {
            volatile float* vS = g_S;
            fS[tid] = vS[tid];
        }
        __syncthreads();
        if (tid < 32) {
            float s = 0.f;
            #pragma unroll
            for (int j = 0; j < 64; j++) s = fmaf(fS[j], W2[j * 32 + tid], s);
            out[tid] = s * (1.0f / (float)N_NODES) + b2[tid];
        }
        if (tid == 0) g_cnt = 0u;     // self-clean for next replay
    }
}

extern "C" void kernel_launch(void* const* d_in, const int* in_sizes, int n_in,
                              void* d_out, int out_size) {
    const float4* x  = (const float4*)d_in[0];   // [100000, 4] f32
    const int*    ei = (const int*)d_in[1];      // [2, E] int32
    const float*  W1 = (const float*)d_in[2];    // [4, 64]
    const float*  b1 = (const float*)d_in[3];    // [64]
    const float*  W2 = (const float*)d_in[4];    // [64, 32]
    const float*  b2 = (const float*)d_in[5];    // [32]
    float*        out = (float*)d_out;           // [32]

    int E  = in_sizes[1] / 2;
    int E4 = E / 4;
    int E8 = (E4 + 1) / 2;                       // threads for 8-edge kernels
    const int4* src4 = (const int4*)ei;
    const int4* dst4 = (const int4*)(ei + E);

    const int T = 256;
    int nb_nodes  = (N_NODES + T - 1) / T;
    int nb_edges8 = (E8 + T - 1) / T;

    k_deg  <<<nb_edges8, T>>>(dst4, E4);
    k_prep <<<nb_nodes, T>>>(x);
    k_edge <<<nb_edges8, T>>>(src4, dst4, E4);
    k_node <<<KN_BLOCKS, KN_THREADS>>>(W1, b1, W2, b2, out);
}